// round 6
// baseline (speedup 1.0000x reference)
#include <cuda_runtime.h>
#include <cuda_bf16.h>

#define MQ 8
#define KQ 4096
#define DG 64
#define NB 32
#define HH 64
#define WW 64
#define H_ITER 4
#define VSTRIDE 68   // floats per smem row: 272B, 16B-aligned, conflict-free

// Scratch LUT: v[m,k,c] = sum_d codebook[m,k,d] * wv[m,c,d]   (8 MB)
__device__ float g_v[MQ * KQ * DG];

typedef unsigned long long ull;

__device__ __forceinline__ void fma2(ull& d, ull a, ull b) {
    asm("fma.rn.f32x2 %0, %1, %2, %3;" : "=l"(d) : "l"(a), "l"(b), "l"(d));
}

// ---------------------------------------------------------------------------
// Phase 1: per-m GEMM  v[m, k, c] = codebook[m,k,:] . wv[m,c,:]
// Packed f32x2 FMA. k-tile 32 -> 1024 blocks for latency hiding.
// 128 threads = (8 kt) x (16 ct); each thread: 4 k-rows x 4 c-cols.
// ---------------------------------------------------------------------------
__global__ __launch_bounds__(128) void compute_v_kernel(
    const float* __restrict__ codebook,   // [M, K, DG]
    const float* __restrict__ wv)         // [M, DG(c), DG(d)]
{
    __shared__ float cb_s[32 * 66];   // [k][d], even stride 66
    __shared__ float wv_s[64 * 66];   // [c][d], even stride 66

    const int m  = blockIdx.y;
    const int k0 = blockIdx.x * 32;
    const int tid = threadIdx.x;

    const float4* cb4 = reinterpret_cast<const float4*>(
        codebook + ((long)m * KQ + k0) * DG);
    const float4* wv4 = reinterpret_cast<const float4*>(wv + m * 64 * 64);
    #pragma unroll
    for (int it = 0; it < 8; it++) {
        int idx = tid + it * 128;
        int r = idx >> 4, d = (idx & 15) * 4;
        float4 b = wv4[idx];
        wv_s[r * 66 + d + 0] = b.x; wv_s[r * 66 + d + 1] = b.y;
        wv_s[r * 66 + d + 2] = b.z; wv_s[r * 66 + d + 3] = b.w;
        if (it < 4) {
            float4 a = cb4[idx];
            cb_s[r * 66 + d + 0] = a.x; cb_s[r * 66 + d + 1] = a.y;
            cb_s[r * 66 + d + 2] = a.z; cb_s[r * 66 + d + 3] = a.w;
        }
    }
    __syncthreads();

    const int kt = tid >> 4;    // 0..7 -> 4 k rows
    const int ct = tid & 15;    // 0..15 -> c = ct + 16*j

    const ull* cbp = reinterpret_cast<const ull*>(cb_s) + (kt * 4) * 33;
    const ull* wvp = reinterpret_cast<const ull*>(wv_s) + ct * 33;

    ull acc[4][4];
    #pragma unroll
    for (int i = 0; i < 4; i++)
        #pragma unroll
        for (int j = 0; j < 4; j++) acc[i][j] = 0ull;

    #pragma unroll 4
    for (int d2 = 0; d2 < 32; d2++) {
        ull b[4];
        #pragma unroll
        for (int j = 0; j < 4; j++) b[j] = wvp[j * 16 * 33 + d2];
        #pragma unroll
        for (int i = 0; i < 4; i++) {
            ull a = cbp[i * 33 + d2];
            fma2(acc[i][0], a, b[0]);
            fma2(acc[i][1], a, b[1]);
            fma2(acc[i][2], a, b[2]);
            fma2(acc[i][3], a, b[3]);
        }
    }

    #pragma unroll
    for (int i = 0; i < 4; i++) {
        int k = k0 + kt * 4 + i;
        float* dst = g_v + ((unsigned)(m * KQ + k)) * DG;
        #pragma unroll
        for (int j = 0; j < 4; j++) {
            float2 p = *reinterpret_cast<float2*>(&acc[i][j]);
            dst[ct + 16 * j] = p.x + p.y;
        }
    }
}

// ---------------------------------------------------------------------------
// Phase 2: pipelined gather + transpose scatter.
// Block (256 thr) = (n, m, 4 h-rows). Register-buffered prefetch.
// Smem tile [w][c] with stride 68 -> STS.128 and LDS.128 both conflict-free.
// ---------------------------------------------------------------------------
__global__ __launch_bounds__(256) void gather_kernel(
    const int* __restrict__ codes,   // [N, H, W, M]
    float* __restrict__ out)         // [N, M*DG, H, W]
{
    __shared__ int   codes_s[H_ITER * 64];
    __shared__ float vs[64 * VSTRIDE];

    const unsigned bid = blockIdx.x;     // [n(5) | m(3) | hg(4)]
    const unsigned hg = bid & 15;
    const unsigned m  = (bid >> 4) & 7;
    const unsigned n  = bid >> 7;
    const unsigned tid = threadIdx.x;
    const unsigned h0 = hg * H_ITER;

    // Load codes for the whole h-group once.
    if (tid < H_ITER * 64) {
        unsigned hh = tid >> 6, w = tid & 63;
        codes_s[tid] = __ldg(&codes[((n * HH + h0 + hh) * WW + w) * MQ + m]);
    }
    __syncthreads();

    // Static per-thread mapping: q constant, 4 rows = tid>>4 + 16*it.
    const unsigned q  = tid & 15;            // float4 index in 256B v-row
    const unsigned r0 = tid >> 4;            // base row (w)
    const float4* gv4 = reinterpret_cast<const float4*>(g_v);
    const unsigned mbase = m * (KQ * (DG / 4));

    // Store-phase mapping
    const unsigned w  = tid & 63;
    const unsigned cb = tid >> 6;            // 0..3 -> c in [cb*16, cb*16+16)
    float* outb = out + (unsigned)((n * 512u + m * 64u) * 4096u) + w;
    const float4* src4 = reinterpret_cast<const float4*>(vs + w * VSTRIDE + cb * 16);

    float4 r[4];
    // Prefetch tile 0
    #pragma unroll
    for (int it = 0; it < 4; it++) {
        unsigned code = (unsigned)codes_s[r0 + 16 * it];
        r[it] = __ldg(&gv4[mbase + code * 16 + q]);
    }

    #pragma unroll
    for (int h = 0; h < H_ITER; h++) {
        // STS current tile: one STS.128 per it, conflict-free.
        #pragma unroll
        for (int it = 0; it < 4; it++) {
            unsigned row = r0 + 16 * it;
            *reinterpret_cast<float4*>(vs + row * VSTRIDE + q * 4) = r[it];
        }
        __syncthreads();

        // Prefetch next tile — overlaps store phase.
        if (h + 1 < H_ITER) {
            #pragma unroll
            for (int it = 0; it < 4; it++) {
                unsigned code = (unsigned)codes_s[(h + 1) * 64 + r0 + 16 * it];
                r[it] = __ldg(&gv4[mbase + code * 16 + q]);
            }
        }

        // Store phase: LDS.128 (conflict-free) + 4 plane-strided STG.32.
        float* outp = outb + (h0 + h) * WW;
        #pragma unroll
        for (int cc4 = 0; cc4 < 4; cc4++) {
            float4 v = src4[cc4];
            unsigned c0 = cb * 16 + cc4 * 4;
            __stcs(&outp[(c0 + 0) * 4096u], v.x);
            __stcs(&outp[(c0 + 1) * 4096u], v.y);
            __stcs(&outp[(c0 + 2) * 4096u], v.z);
            __stcs(&outp[(c0 + 3) * 4096u], v.w);
        }
        __syncthreads();
    }
}

extern "C" void kernel_launch(void* const* d_in, const int* in_sizes, int n_in,
                              void* d_out, int out_size)
{
    const int*   codes    = (const int*)d_in[0];    // (32,64,64,8) int32
    const float* codebook = (const float*)d_in[1];  // (8,4096,64) fp32
    const float* wv       = (const float*)d_in[2];  // (8,64,64) fp32
    float*       out      = (float*)d_out;          // (32,512,64,64) fp32

    (void)in_sizes; (void)n_in; (void)out_size;

    dim3 g1(KQ / 32, MQ);
    compute_v_kernel<<<g1, 128>>>(codebook, wv);

    // 32 * 8 * 16 = 4096 blocks, one per (n, m, h-group of 4)
    gather_kernel<<<NB * MQ * (HH / H_ITER), 256>>>(codes, out);
}

// round 7
// speedup vs baseline: 1.8119x; 1.8119x over previous
#include <cuda_runtime.h>
#include <cuda_fp16.h>
#include <cuda_bf16.h>

#define MQ 8
#define KQ 4096
#define DG 64
#define NB 32
#define HH 64
#define WW 64
#define H_ITER 16
#define RSTRIDE 36   // uints per smem row (144B): STS.128/LDS.128 aligned

// Scratch LUT in fp16: v[m,k,c]  (4 MB). uint4-typed for 16B alignment.
__device__ uint4 g_v4[MQ * KQ * (DG / 8)];

typedef unsigned long long ull;

__device__ __forceinline__ void fma2(ull& d, ull a, ull b) {
    asm("fma.rn.f32x2 %0, %1, %2, %3;" : "=l"(d) : "l"(a), "l"(b), "l"(d));
}

// ---------------------------------------------------------------------------
// Phase 1: per-m GEMM  v[m, k, c] = codebook[m,k,:] . wv[m,c,:]
// R3-proven structure (64 k-tile, packed f32x2 FMA); output stored as fp16.
// ---------------------------------------------------------------------------
__global__ __launch_bounds__(128) void compute_v_kernel(
    const float* __restrict__ codebook,   // [M, K, DG]
    const float* __restrict__ wv)         // [M, DG(c), DG(d)]
{
    __shared__ float cb_s[64 * 66];
    __shared__ float wv_s[64 * 66];

    const int m  = blockIdx.y;
    const int k0 = blockIdx.x * 64;
    const int tid = threadIdx.x;

    const float4* cb4 = reinterpret_cast<const float4*>(
        codebook + ((long)m * KQ + k0) * DG);
    const float4* wv4 = reinterpret_cast<const float4*>(wv + m * 64 * 64);
    #pragma unroll
    for (int it = 0; it < 8; it++) {
        int idx = tid + it * 128;
        int r = idx >> 4, d = (idx & 15) * 4;
        float4 a = cb4[idx];
        cb_s[r * 66 + d + 0] = a.x; cb_s[r * 66 + d + 1] = a.y;
        cb_s[r * 66 + d + 2] = a.z; cb_s[r * 66 + d + 3] = a.w;
        float4 b = wv4[idx];
        wv_s[r * 66 + d + 0] = b.x; wv_s[r * 66 + d + 1] = b.y;
        wv_s[r * 66 + d + 2] = b.z; wv_s[r * 66 + d + 3] = b.w;
    }
    __syncthreads();

    const int kt = tid >> 4;
    const int ct = tid & 15;

    const ull* cbp = reinterpret_cast<const ull*>(cb_s) + (kt * 8) * 33;
    const ull* wvp = reinterpret_cast<const ull*>(wv_s) + ct * 33;

    ull acc[8][4];
    #pragma unroll
    for (int i = 0; i < 8; i++)
        #pragma unroll
        for (int j = 0; j < 4; j++) acc[i][j] = 0ull;

    #pragma unroll 2
    for (int d2 = 0; d2 < 32; d2++) {
        ull b[4];
        #pragma unroll
        for (int j = 0; j < 4; j++) b[j] = wvp[j * 16 * 33 + d2];
        #pragma unroll
        for (int i = 0; i < 8; i++) {
            ull a = cbp[i * 33 + d2];
            fma2(acc[i][0], a, b[0]);
            fma2(acc[i][1], a, b[1]);
            fma2(acc[i][2], a, b[2]);
            fma2(acc[i][3], a, b[3]);
        }
    }

    __half* gvh = reinterpret_cast<__half*>(g_v4);
    #pragma unroll
    for (int i = 0; i < 8; i++) {
        int k = k0 + kt * 8 + i;
        __half* dst = gvh + ((unsigned)(m * KQ + k)) * DG;
        #pragma unroll
        for (int j = 0; j < 4; j++) {
            float2 p = *reinterpret_cast<float2*>(&acc[i][j]);
            dst[ct + 16 * j] = __float2half(p.x + p.y);
        }
    }
}

// ---------------------------------------------------------------------------
// Phase 2: pipelined gather (fp16 LUT) + transpose scatter.
// Block (256 thr) = (n, m, 16 h-rows). Register-buffered prefetch (R5-style).
// Smem tile: 64 rows x 36 uints (row = 32 uints of half2 + pad).
// uint4-slot swizzle s ^= 2*(row&3): STS.128 and LDS.128 both conflict-free.
// ---------------------------------------------------------------------------
__global__ __launch_bounds__(256) void gather_kernel(
    const int* __restrict__ codes,   // [N, H, W, M]
    float* __restrict__ out)         // [N, M*DG, H, W]
{
    __shared__ int  codes_s[H_ITER * 64];
    __shared__ uint4 vsq[64 * (RSTRIDE / 4) + 16];  // 64 rows x 9 uint4-slots

    unsigned* vsu = reinterpret_cast<unsigned*>(vsq);

    const unsigned bid = blockIdx.x;     // [n(5) | m(3) | hg(2)]
    const unsigned hg = bid & 3;
    const unsigned m  = (bid >> 2) & 7;
    const unsigned n  = bid >> 5;
    const unsigned tid = threadIdx.x;
    const unsigned h0 = hg * H_ITER;

    // Load codes for the whole h-group once.
    #pragma unroll
    for (int i = tid; i < H_ITER * 64; i += 256) {
        unsigned hh = (unsigned)i >> 6, w = (unsigned)i & 63;
        codes_s[i] = __ldg(&codes[((n * HH + h0 + hh) * WW + w) * MQ + m]);
    }
    __syncthreads();

    // Load mapping: q = uint4-slot (0..7) within the 128B fp16 row;
    // rows rw and rw+32 per thread.
    const unsigned q  = tid & 7;
    const unsigned rw = tid >> 3;            // 0..31
    const uint4* gv = g_v4;
    const unsigned mbase = m * (KQ * 8u);    // uint4 units

    // Store-phase mapping
    const unsigned w  = tid & 63;
    const unsigned cb = tid >> 6;            // 0..3 -> c in [cb*16, cb*16+16)
    float* outb = out + (unsigned)((n * 512u + m * 64u) * 4096u) + w;
    const unsigned wsw = 2u * (w & 3);       // slot swizzle for row w
    const unsigned lbase = w * (RSTRIDE / 4);  // uint4 index of row w

    uint4 r0v, r1v;
    // Prefetch tile 0
    {
        unsigned c0 = (unsigned)codes_s[rw];
        unsigned c1 = (unsigned)codes_s[rw + 32];
        r0v = __ldg(&gv[mbase + c0 * 8 + q]);
        r1v = __ldg(&gv[mbase + c1 * 8 + q]);
    }

    const unsigned s0 = rw * RSTRIDE + 4 * (q ^ (2u * (rw & 3)));
    const unsigned s1 = (rw + 32) * RSTRIDE + 4 * (q ^ (2u * (rw & 3)));

    #pragma unroll 4
    for (int h = 0; h < H_ITER; h++) {
        // STS current tile: swizzled STS.128, conflict-free.
        *reinterpret_cast<uint4*>(vsu + s0) = r0v;
        *reinterpret_cast<uint4*>(vsu + s1) = r1v;
        __syncthreads();

        // Prefetch next tile — overlaps the store phase.
        if (h + 1 < H_ITER) {
            unsigned c0 = (unsigned)codes_s[(h + 1) * 64 + rw];
            unsigned c1 = (unsigned)codes_s[(h + 1) * 64 + rw + 32];
            r0v = __ldg(&gv[mbase + c0 * 8 + q]);
            r1v = __ldg(&gv[mbase + c1 * 8 + q]);
        }

        // Store phase: 2 swizzled LDS.128 -> cvt -> 16 coalesced STG.32.
        float* outp = outb + (h0 + (unsigned)h) * WW;
        #pragma unroll
        for (int sl = 0; sl < 2; sl++) {
            unsigned slot = (2u * cb + (unsigned)sl) ^ wsw;
            uint4 u = vsq[lbase + slot];
            unsigned c0 = cb * 16 + (unsigned)sl * 8;
            float2 f;
            f = __half22float2(*reinterpret_cast<__half2*>(&u.x));
            __stcs(&outp[(c0 + 0) * 4096u], f.x);
            __stcs(&outp[(c0 + 1) * 4096u], f.y);
            f = __half22float2(*reinterpret_cast<__half2*>(&u.y));
            __stcs(&outp[(c0 + 2) * 4096u], f.x);
            __stcs(&outp[(c0 + 3) * 4096u], f.y);
            f = __half22float2(*reinterpret_cast<__half2*>(&u.z));
            __stcs(&outp[(c0 + 4) * 4096u], f.x);
            __stcs(&outp[(c0 + 5) * 4096u], f.y);
            f = __half22float2(*reinterpret_cast<__half2*>(&u.w));
            __stcs(&outp[(c0 + 6) * 4096u], f.x);
            __stcs(&outp[(c0 + 7) * 4096u], f.y);
        }
        __syncthreads();
    }
}

extern "C" void kernel_launch(void* const* d_in, const int* in_sizes, int n_in,
                              void* d_out, int out_size)
{
    const int*   codes    = (const int*)d_in[0];    // (32,64,64,8) int32
    const float* codebook = (const float*)d_in[1];  // (8,4096,64) fp32
    const float* wv       = (const float*)d_in[2];  // (8,64,64) fp32
    float*       out      = (float*)d_out;          // (32,512,64,64) fp32

    (void)in_sizes; (void)n_in; (void)out_size;

    dim3 g1(KQ / 64, MQ);
    compute_v_kernel<<<g1, 128>>>(codebook, wv);

    // 32 * 8 * 4 = 1024 blocks, one per (n, m, 16-h group): single wave
    gather_kernel<<<NB * MQ * (HH / H_ITER), 256>>>(codes, out);
}